// round 5
// baseline (speedup 1.0000x reference)
#include <cuda_runtime.h>
#include <cuda_bf16.h>
#include <math.h>

#define B_SZ 512
#define K_SZ 32
#define D_SZ 768
#define N_SENSES 200000
#define NEG_INF -1e30f

#define WARPS_PER_CTA 8
#define CTA_THREADS (WARPS_PER_CTA * 32)
#define GRID_CTAS ((B_SZ * K_SZ) / WARPS_PER_CTA)   // 2048

// Global scratch. All counters use atomicInc with wrap so they self-reset to 0
// after every complete launch -> deterministic under graph replay.
__device__ float    g_logits[B_SZ * K_SZ];
__device__ float    g_nll[B_SZ];
__device__ unsigned g_cnt[B_SZ];     // per-sample arrival counter (wraps at K_SZ-1)
__device__ unsigned g_done = 0;      // sample-completion counter (wraps at B_SZ-1)

__global__ __launch_bounds__(CTA_THREADS)
void cbert_flat_kernel(const float* __restrict__ reps,
                       const float* __restrict__ weight,
                       const float* __restrict__ bias,
                       const int* __restrict__ sense_ids,
                       const int* __restrict__ target_ids,
                       float* __restrict__ out, int out_size) {
    const int lane = threadIdx.x & 31;
    const int gwarp = blockIdx.x * WARPS_PER_CTA + (threadIdx.x >> 5);
    const int b = gwarp >> 5;          // sample
    const int k = gwarp & 31;          // candidate slot

    // ---- Phase 1: logit for (b, k) ----
    const int id = sense_ids[b * K_SZ + k];
    float logit = NEG_INF;
    if (id >= 0 && id < N_SENSES) {
        const float4* wrow = reinterpret_cast<const float4*>(weight + (size_t)id * D_SZ);
        const float4* rrow = reinterpret_cast<const float4*>(reps + (size_t)b * D_SZ);
        float acc = 0.f;
        // 192 float4 per row, 32 lanes -> 6 float4 each of weight + reps (MLP=12)
        #pragma unroll
        for (int j = 0; j < 6; ++j) {
            const int i = lane + 32 * j;
            float4 w4 = wrow[i];
            float4 r4 = __ldg(&rrow[i]);
            acc = fmaf(w4.x, r4.x, acc);
            acc = fmaf(w4.y, r4.y, acc);
            acc = fmaf(w4.z, r4.z, acc);
            acc = fmaf(w4.w, r4.w, acc);
        }
        #pragma unroll
        for (int off = 16; off > 0; off >>= 1)
            acc += __shfl_down_sync(0xFFFFFFFFu, acc, off);
        if (lane == 0) logit = acc + bias[id];
    }

    unsigned old = 0;
    if (lane == 0) {
        __stcg(&g_logits[b * K_SZ + k], logit);   // L2-visible, bypass L1
        __threadfence();
        old = atomicInc(&g_cnt[b], K_SZ - 1);     // wraps to 0 after 32 arrivals
    }
    old = __shfl_sync(0xFFFFFFFFu, old, 0);
    if (old != K_SZ - 1) return;                  // not the last candidate of b

    // ---- Phase 2: this warp is the last arrival for sample b -> softmax ----
    __threadfence();                               // order counter read before loads
    float v = __ldcg(&g_logits[b * K_SZ + lane]);

    // max + first-index argmax (larger wins; tie -> smaller index)
    float mval = v; int midx = lane;
    #pragma unroll
    for (int off = 16; off > 0; off >>= 1) {
        float ov = __shfl_down_sync(0xFFFFFFFFu, mval, off);
        int   oi = __shfl_down_sync(0xFFFFFFFFu, midx, off);
        if (ov > mval || (ov == mval && oi < midx)) { mval = ov; midx = oi; }
    }
    mval = __shfl_sync(0xFFFFFFFFu, mval, 0);
    midx = __shfl_sync(0xFFFFFFFFu, midx, 0);

    float e = expf(v - mval);
    #pragma unroll
    for (int off = 16; off > 0; off >>= 1)
        e += __shfl_down_sync(0xFFFFFFFFu, e, off);
    float sumexp = __shfl_sync(0xFFFFFFFFu, e, 0);

    const int tgt = target_ids[b];
    float tlogit = __shfl_sync(0xFFFFFFFFu, v, tgt & 31);

    unsigned done = 0;
    if (lane == 0) {
        float nll = -(tlogit - mval - logf(sumexp));
        __stcg(&g_nll[b], nll);
        if (1 + b < out_size) out[1 + b] = (midx == tgt) ? 1.0f : 0.0f;
        __threadfence();
        done = atomicInc(&g_done, B_SZ - 1);      // wraps to 0 after 512 samples
    }
    done = __shfl_sync(0xFFFFFFFFu, done, 0);
    if (done != B_SZ - 1) return;

    // ---- Phase 3: last sample done -> deterministic mean of 512 NLLs ----
    __threadfence();
    float acc = 0.f;
    #pragma unroll
    for (int i = 0; i < B_SZ / 32; ++i)           // fixed order: lane-strided
        acc += __ldcg(&g_nll[lane + 32 * i]);
    #pragma unroll
    for (int off = 16; off > 0; off >>= 1)        // fixed shuffle tree
        acc += __shfl_down_sync(0xFFFFFFFFu, acc, off);
    if (lane == 0 && out_size > 0) out[0] = acc / (float)B_SZ;
}

extern "C" void kernel_launch(void* const* d_in, const int* in_sizes, int n_in,
                              void* d_out, int out_size) {
    const float* reps = (const float*)d_in[0];
    const float* weight = (const float*)d_in[1];
    const float* bias = (const float*)d_in[2];
    const int* sense_ids = (const int*)d_in[3];
    const int* target_ids = (const int*)d_in[4];
    float* out = (float*)d_out;

    cbert_flat_kernel<<<GRID_CTAS, CTA_THREADS>>>(reps, weight, bias,
                                                  sense_ids, target_ids,
                                                  out, out_size);
}